// round 6
// baseline (speedup 1.0000x reference)
#include <cuda_runtime.h>
#include <math.h>
#include <stdint.h>

#define BB 4
#define CC 64
#define NN 4096
#define TQa 128
#define TKa 64
#define WSTRIDE 68
#define NTILE (NN / TKa)   // 64 tiles per batch

// Scratch (__device__ globals). K/V stored PRE-PACKED in mma-fragment order.
__device__ float g_q[BB * NN * CC];        // (b, n, c) token-major, tf32, 1/N folded
__device__ float g_kp[BB * NTILE * 4096];  // packed K tiles
__device__ float g_vp[BB * NTILE * 4096];  // packed V tiles

// ---------------------------------------------------------------------------
__device__ __forceinline__ float to_tf32(float x) {
    uint32_t u;
    asm("cvt.rna.tf32.f32 %0, %1;" : "=r"(u) : "f"(x));
    return __uint_as_float(u);
}
__device__ __forceinline__ uint32_t smem_u32(const void* p) {
    uint32_t a;
    asm("{ .reg .u64 t; cvta.to.shared.u64 t, %1; cvt.u32.u64 %0, t; }" : "=r"(a) : "l"(p));
    return a;
}
__device__ __forceinline__ void cp16(uint32_t dst, const void* src) {
    asm volatile("cp.async.cg.shared.global [%0], [%1], 16;" :: "r"(dst), "l"(src));
}
__device__ __forceinline__ void cp_commit() { asm volatile("cp.async.commit_group;"); }
__device__ __forceinline__ void cp_wait1() { asm volatile("cp.async.wait_group 1;"); }
__device__ __forceinline__ void cp_wait0() { asm volatile("cp.async.wait_group 0;"); }

__device__ __forceinline__ void mma8(float* d, uint32_t a0, uint32_t a1,
                                     uint32_t a2, uint32_t a3,
                                     uint32_t b0, uint32_t b1) {
    asm volatile(
        "mma.sync.aligned.m16n8k8.row.col.f32.tf32.tf32.f32 "
        "{%0,%1,%2,%3}, {%4,%5,%6,%7}, {%8,%9}, {%0,%1,%2,%3};"
        : "+f"(d[0]), "+f"(d[1]), "+f"(d[2]), "+f"(d[3])
        : "r"(a0), "r"(a1), "r"(a2), "r"(a3), "r"(b0), "r"(b1));
}

// Packed-fragment index maps (j = token within 64-tile, c = channel)
__device__ __forceinline__ int idxK(int j, int c) {
    return (((c >> 4) * 8 + (j >> 3)) * 32 + (j & 7) * 4) * 4 + ((c >> 2) & 3) + 4 * (c & 3);
}
__device__ __forceinline__ int idxV(int j, int c) {
    return (((j >> 4) * 8 + (c >> 3)) * 32 + (c & 7) * 4) * 4 + ((j >> 2) & 3) + 4 * (j & 3);
}

// ---------------------------------------------------------------------------
// Kernel 1: fused QKV projection; block == one 64-token tile, so K/V can be
// written directly in packed fragment order.
// ---------------------------------------------------------------------------
__global__ void __launch_bounds__(256) proj_kernel(
    const float* __restrict__ x,
    const float* __restrict__ wq, const float* __restrict__ bq,
    const float* __restrict__ wk, const float* __restrict__ bk,
    const float* __restrict__ wv, const float* __restrict__ bv)
{
    extern __shared__ float sm[];
    float* Xs = sm;               // [C][64]
    float* Ws = sm + CC * 64;     // [3][C][WSTRIDE]

    const int b  = blockIdx.y;
    const int tile = blockIdx.x;
    const int n0 = tile * 64;
    const int tid = threadIdx.x;

    {
        int row = tid >> 2;
        int col = (tid & 3) * 16;
        const float* src = x + ((size_t)(b * CC + row) * NN + n0 + col);
        float* dst = Xs + row * 64 + col;
        #pragma unroll
        for (int k = 0; k < 16; k += 4)
            *(float4*)(dst + k) = *(const float4*)(src + k);
    }
    {
        const float* wsrc[3] = {wq, wk, wv};
        #pragma unroll
        for (int m = 0; m < 3; m++) {
            const float* w = wsrc[m];
            for (int idx = tid; idx < CC * CC; idx += 256) {
                int o = idx >> 6, c = idx & 63;
                Ws[(m * CC + c) * WSTRIDE + o] = w[idx];
            }
        }
    }
    __syncthreads();

    const int ti = tid >> 4, tj = tid & 15;
    const int o0 = ti * 4, nn0 = tj * 4;

    float acc[3][4][4];
    #pragma unroll
    for (int m = 0; m < 3; m++)
        #pragma unroll
        for (int i = 0; i < 4; i++)
            #pragma unroll
            for (int j = 0; j < 4; j++) acc[m][i][j] = 0.f;

    #pragma unroll 4
    for (int c = 0; c < CC; c++) {
        float4 x4 = *(float4*)(Xs + c * 64 + nn0);
        float xv[4] = {x4.x, x4.y, x4.z, x4.w};
        #pragma unroll
        for (int m = 0; m < 3; m++) {
            float4 w4 = *(float4*)(Ws + (m * CC + c) * WSTRIDE + o0);
            float wv_[4] = {w4.x, w4.y, w4.z, w4.w};
            #pragma unroll
            for (int oo = 0; oo < 4; oo++)
                #pragma unroll
                for (int nn = 0; nn < 4; nn++)
                    acc[m][oo][nn] += wv_[oo] * xv[nn];
        }
    }

    const float invN = 1.0f / (float)NN;
    float bqv[4], bkv[4], bvv[4];
    #pragma unroll
    for (int oo = 0; oo < 4; oo++) {
        bqv[oo] = bq[o0 + oo];
        bkv[oo] = bk[o0 + oo];
        bvv[oo] = bv[o0 + oo];
    }
    // Q (scaled, tf32) token-major
    #pragma unroll
    for (int nn = 0; nn < 4; nn++) {
        int token = n0 + nn0 + nn;
        float4 qo = make_float4(to_tf32((acc[0][0][nn] + bqv[0]) * invN),
                                to_tf32((acc[0][1][nn] + bqv[1]) * invN),
                                to_tf32((acc[0][2][nn] + bqv[2]) * invN),
                                to_tf32((acc[0][3][nn] + bqv[3]) * invN));
        *(float4*)(g_q + (size_t)(b * NN + token) * CC + o0) = qo;
    }
    // K and V packed fragment stores
    float* kdst = g_kp + (size_t)(b * NTILE + tile) * 4096;
    float* vdst = g_vp + (size_t)(b * NTILE + tile) * 4096;
    #pragma unroll
    for (int oo = 0; oo < 4; oo++) {
        int c = o0 + oo;
        #pragma unroll
        for (int nn = 0; nn < 4; nn++) {
            int j = nn0 + nn;
            kdst[idxK(j, c)] = to_tf32(acc[1][oo][nn] + bkv[oo]);
            vdst[idxV(j, c)] = to_tf32(acc[2][oo][nn] + bvv[oo]);
        }
    }
}

// ---------------------------------------------------------------------------
// Kernel 2: mma.sync tf32 flash attention, 8 warps (16 rows each),
// cp.async double-buffered K/V, Q fragments resident in registers.
// SMEM (floats): Kb[2][4096] | Vb[2][4096] | Ps[8][1088]
// ---------------------------------------------------------------------------
__global__ void __launch_bounds__(256, 1) attn_mma_kernel(float* __restrict__ out)
{
    extern __shared__ float sm[];
    float* Kb = sm;            // 2 x 4096
    float* Vb = sm + 8192;     // 2 x 4096
    float* Ps = sm + 16384;    // 8 x 1088

    const int b  = blockIdx.y;
    const int q0 = blockIdx.x * TQa;
    const int tid = threadIdx.x, w = tid >> 5, lam = tid & 31;
    const int g = lam >> 2, tau = lam & 3;
    const uint32_t smK = smem_u32(Kb), smV = smem_u32(Vb);

    // Q A-fragments in registers (warp owns rows w*16 .. w*16+15)
    uint32_t qa[8][4];
    {
        const float* qb = g_q + (size_t)(b * NN + q0 + w * 16) * CC;
        #pragma unroll
        for (int s = 0; s < 8; s++) {
            int c = tau + 8 * s;
            qa[s][0] = __float_as_uint(qb[g * CC + c]);
            qa[s][1] = __float_as_uint(qb[(g + 8) * CC + c]);
            qa[s][2] = __float_as_uint(qb[g * CC + c + 4]);
            qa[s][3] = __float_as_uint(qb[(g + 8) * CC + c + 4]);
        }
    }

    float of[8][4];
    #pragma unroll
    for (int t = 0; t < 8; t++)
        #pragma unroll
        for (int c = 0; c < 4; c++) of[t][c] = 0.f;
    float lA = 0.f, lB = 0.f;

    const float* kp = g_kp + (size_t)b * NTILE * 4096;
    const float* vp = g_vp + (size_t)b * NTILE * 4096;
    float* Pw = Ps + w * 1088;

    // prologue: load tile 0 into buffer 0
    #pragma unroll
    for (int r = 0; r < 4; r++) {
        int i = tid + 256 * r;
        cp16(smK + i * 16, kp + i * 4);
        cp16(smV + i * 16, vp + i * 4);
    }
    cp_commit();

    for (int kt = 0; kt < NTILE; kt++) {
        if (kt < NTILE - 1) {
            uint32_t nbb = (uint32_t)((kt + 1) & 1) * 16384u;  // byte offset of buffer
            const float* ksrc = kp + (size_t)(kt + 1) * 4096;
            const float* vsrc = vp + (size_t)(kt + 1) * 4096;
            #pragma unroll
            for (int r = 0; r < 4; r++) {
                int i = tid + 256 * r;
                cp16(smK + nbb + i * 16, ksrc + i * 4);
                cp16(smV + nbb + i * 16, vsrc + i * 4);
            }
            cp_commit();
            cp_wait1();
        } else {
            cp_wait0();
        }
        __syncthreads();

        const float* Kp = Kb + (kt & 1) * 4096;
        const float* Vp = Vb + (kt & 1) * 4096;

        // ---- MMA1: S = Q K^T ----
        float sf[8][4];
        #pragma unroll
        for (int t = 0; t < 8; t++)
            #pragma unroll
            for (int c = 0; c < 4; c++) sf[t][c] = 0.f;

        #pragma unroll
        for (int s2 = 0; s2 < 4; s2++) {
            #pragma unroll
            for (int t = 0; t < 8; t++) {
                uint4 kb = *(uint4*)(Kp + ((s2 * 8 + t) * 32 + lam) * 4);
                mma8(sf[t], qa[2 * s2][0], qa[2 * s2][1], qa[2 * s2][2], qa[2 * s2][3], kb.x, kb.y);
                mma8(sf[t], qa[2 * s2 + 1][0], qa[2 * s2 + 1][1], qa[2 * s2 + 1][2], qa[2 * s2 + 1][3], kb.z, kb.w);
            }
        }

        // ---- softmax (no max: |S| << 1); P -> SMEM (tf32) ----
        float rs0 = 0.f, rs1 = 0.f;
        #pragma unroll
        for (int t = 0; t < 8; t++) {
            float e0 = __expf(sf[t][0]);
            float e1 = __expf(sf[t][1]);
            float e2 = __expf(sf[t][2]);
            float e3 = __expf(sf[t][3]);
            rs0 += e0 + e1;
            rs1 += e2 + e3;
            int col = 8 * t + 2 * tau;
            *(float2*)(Pw + g * 68 + col)       = make_float2(to_tf32(e0), to_tf32(e1));
            *(float2*)(Pw + (g + 8) * 68 + col) = make_float2(to_tf32(e2), to_tf32(e3));
        }
        rs0 += __shfl_xor_sync(0xffffffffu, rs0, 1);
        rs0 += __shfl_xor_sync(0xffffffffu, rs0, 2);
        rs1 += __shfl_xor_sync(0xffffffffu, rs1, 1);
        rs1 += __shfl_xor_sync(0xffffffffu, rs1, 2);
        lA += rs0;
        lB += rs1;
        __syncwarp();

        // ---- MMA2: O += P V ----
        #pragma unroll
        for (int s2 = 0; s2 < 4; s2++) {
            uint32_t pa[2][4];
            #pragma unroll
            for (int h = 0; h < 2; h++) {
                int colb = tau + 8 * (2 * s2 + h);
                pa[h][0] = __float_as_uint(Pw[g * 68 + colb]);
                pa[h][1] = __float_as_uint(Pw[(g + 8) * 68 + colb]);
                pa[h][2] = __float_as_uint(Pw[g * 68 + colb + 4]);
                pa[h][3] = __float_as_uint(Pw[(g + 8) * 68 + colb + 4]);
            }
            #pragma unroll
            for (int t = 0; t < 8; t++) {
                uint4 vb = *(uint4*)(Vp + ((s2 * 8 + t) * 32 + lam) * 4);
                mma8(of[t], pa[0][0], pa[0][1], pa[0][2], pa[0][3], vb.x, vb.y);
                mma8(of[t], pa[1][0], pa[1][1], pa[1][2], pa[1][3], vb.z, vb.w);
            }
        }
        __syncthreads();
    }

    // ---- epilogue ----
    const float invA = 1.f / lA, invB = 1.f / lB;
    const int rowa = q0 + w * 16 + g;
    #pragma unroll
    for (int t = 0; t < 8; t++) {
        int col = 8 * t + 2 * tau;
        out[(size_t)(b * CC + col)     * NN + rowa]     = of[t][0] * invA;
        out[(size_t)(b * CC + col + 1) * NN + rowa]     = of[t][1] * invA;
        out[(size_t)(b * CC + col)     * NN + rowa + 8] = of[t][2] * invB;
        out[(size_t)(b * CC + col + 1) * NN + rowa + 8] = of[t][3] * invB;
    }
}

// ---------------------------------------------------------------------------
extern "C" void kernel_launch(void* const* d_in, const int* in_sizes, int n_in,
                              void* d_out, int out_size)
{
    const float* x  = (const float*)d_in[0];
    const float* wq = (const float*)d_in[1];
    const float* bq = (const float*)d_in[2];
    const float* wk = (const float*)d_in[3];
    const float* bk = (const float*)d_in[4];
    const float* wv = (const float*)d_in[5];
    const float* bv = (const float*)d_in[6];
    float* out = (float*)d_out;

    const int smem_proj = (CC * 64 + 3 * CC * WSTRIDE) * sizeof(float);
    const int smem_attn = (8192 + 8192 + 8 * 1088) * sizeof(float);  // 100352 B
    cudaFuncSetAttribute(proj_kernel, cudaFuncAttributeMaxDynamicSharedMemorySize, smem_proj);
    cudaFuncSetAttribute(attn_mma_kernel, cudaFuncAttributeMaxDynamicSharedMemorySize, smem_attn);

    dim3 gp(NN / 64, BB);
    proj_kernel<<<gp, 256, smem_proj>>>(x, wq, bq, wk, bk, wv, bv);
    dim3 ga(NN / TQa, BB);
    attn_mma_kernel<<<ga, 256, smem_attn>>>(out);
}

// round 7
// speedup vs baseline: 1.7047x; 1.7047x over previous
#include <cuda_runtime.h>
#include <math.h>
#include <stdint.h>

#define BB 4
#define CC 64
#define NN 4096
#define TQa 128
#define TKa 64
#define WSTRIDE 68
#define NTILE (NN / TKa)   // 64 tiles per batch
#define NSPLIT 2
#define TPS (NTILE / NSPLIT)  // 32 tiles per split

// Scratch (__device__ globals). K/V stored PRE-PACKED in mma-fragment order.
__device__ float g_q[BB * NN * CC];        // (b, n, c) token-major, tf32, 1/N folded
__device__ float g_kp[BB * NTILE * 4096];  // packed K tiles
__device__ float g_vp[BB * NTILE * 4096];  // packed V tiles
__device__ float g_po[NSPLIT * BB * CC * NN];  // unnormalized O partials
__device__ float g_pl[NSPLIT * BB * NN];       // row-sum partials

// ---------------------------------------------------------------------------
__device__ __forceinline__ float to_tf32(float x) {
    uint32_t u;
    asm("cvt.rna.tf32.f32 %0, %1;" : "=r"(u) : "f"(x));
    return __uint_as_float(u);
}
__device__ __forceinline__ uint32_t smem_u32(const void* p) {
    uint32_t a;
    asm("{ .reg .u64 t; cvta.to.shared.u64 t, %1; cvt.u32.u64 %0, t; }" : "=r"(a) : "l"(p));
    return a;
}
__device__ __forceinline__ void cp16(uint32_t dst, const void* src) {
    asm volatile("cp.async.cg.shared.global [%0], [%1], 16;" :: "r"(dst), "l"(src));
}
__device__ __forceinline__ void cp_commit() { asm volatile("cp.async.commit_group;"); }
__device__ __forceinline__ void cp_wait0() { asm volatile("cp.async.wait_group 0;"); }

__device__ __forceinline__ void mma8(float* d, uint32_t a0, uint32_t a1,
                                     uint32_t a2, uint32_t a3,
                                     uint32_t b0, uint32_t b1) {
    asm volatile(
        "mma.sync.aligned.m16n8k8.row.col.f32.tf32.tf32.f32 "
        "{%0,%1,%2,%3}, {%4,%5,%6,%7}, {%8,%9}, {%0,%1,%2,%3};"
        : "+f"(d[0]), "+f"(d[1]), "+f"(d[2]), "+f"(d[3])
        : "r"(a0), "r"(a1), "r"(a2), "r"(a3), "r"(b0), "r"(b1));
}

// Packed-fragment index maps (j = token within 64-tile, c = channel)
__device__ __forceinline__ int idxK(int j, int c) {
    return (((c >> 4) * 8 + (j >> 3)) * 32 + (j & 7) * 4) * 4 + ((c >> 2) & 3) + 4 * (c & 3);
}
__device__ __forceinline__ int idxV(int j, int c) {
    return (((j >> 4) * 8 + (c >> 3)) * 32 + (c & 7) * 4) * 4 + ((j >> 2) & 3) + 4 * (j & 3);
}

// ---------------------------------------------------------------------------
// Kernel 1: fused QKV projection; block == one 64-token tile, K/V written
// directly in packed fragment order.
// ---------------------------------------------------------------------------
__global__ void __launch_bounds__(256) proj_kernel(
    const float* __restrict__ x,
    const float* __restrict__ wq, const float* __restrict__ bq,
    const float* __restrict__ wk, const float* __restrict__ bk,
    const float* __restrict__ wv, const float* __restrict__ bv)
{
    extern __shared__ float sm[];
    float* Xs = sm;               // [C][64]
    float* Ws = sm + CC * 64;     // [3][C][WSTRIDE]

    const int b  = blockIdx.y;
    const int tile = blockIdx.x;
    const int n0 = tile * 64;
    const int tid = threadIdx.x;

    {
        int row = tid >> 2;
        int col = (tid & 3) * 16;
        const float* src = x + ((size_t)(b * CC + row) * NN + n0 + col);
        float* dst = Xs + row * 64 + col;
        #pragma unroll
        for (int k = 0; k < 16; k += 4)
            *(float4*)(dst + k) = *(const float4*)(src + k);
    }
    {
        const float* wsrc[3] = {wq, wk, wv};
        #pragma unroll
        for (int m = 0; m < 3; m++) {
            const float* w = wsrc[m];
            for (int idx = tid; idx < CC * CC; idx += 256) {
                int o = idx >> 6, c = idx & 63;
                Ws[(m * CC + c) * WSTRIDE + o] = w[idx];
            }
        }
    }
    __syncthreads();

    const int ti = tid >> 4, tj = tid & 15;
    const int o0 = ti * 4, nn0 = tj * 4;

    float acc[3][4][4];
    #pragma unroll
    for (int m = 0; m < 3; m++)
        #pragma unroll
        for (int i = 0; i < 4; i++)
            #pragma unroll
            for (int j = 0; j < 4; j++) acc[m][i][j] = 0.f;

    #pragma unroll 4
    for (int c = 0; c < CC; c++) {
        float4 x4 = *(float4*)(Xs + c * 64 + nn0);
        float xv[4] = {x4.x, x4.y, x4.z, x4.w};
        #pragma unroll
        for (int m = 0; m < 3; m++) {
            float4 w4 = *(float4*)(Ws + (m * CC + c) * WSTRIDE + o0);
            float wv_[4] = {w4.x, w4.y, w4.z, w4.w};
            #pragma unroll
            for (int oo = 0; oo < 4; oo++)
                #pragma unroll
                for (int nn = 0; nn < 4; nn++)
                    acc[m][oo][nn] += wv_[oo] * xv[nn];
        }
    }

    const float invN = 1.0f / (float)NN;
    float bqv[4], bkv[4], bvv[4];
    #pragma unroll
    for (int oo = 0; oo < 4; oo++) {
        bqv[oo] = bq[o0 + oo];
        bkv[oo] = bk[o0 + oo];
        bvv[oo] = bv[o0 + oo];
    }
    // Q (scaled, tf32) token-major
    #pragma unroll
    for (int nn = 0; nn < 4; nn++) {
        int token = n0 + nn0 + nn;
        float4 qo = make_float4(to_tf32((acc[0][0][nn] + bqv[0]) * invN),
                                to_tf32((acc[0][1][nn] + bqv[1]) * invN),
                                to_tf32((acc[0][2][nn] + bqv[2]) * invN),
                                to_tf32((acc[0][3][nn] + bqv[3]) * invN));
        *(float4*)(g_q + (size_t)(b * NN + token) * CC + o0) = qo;
    }
    // K and V packed fragment stores
    float* kdst = g_kp + (size_t)(b * NTILE + tile) * 4096;
    float* vdst = g_vp + (size_t)(b * NTILE + tile) * 4096;
    #pragma unroll
    for (int oo = 0; oo < 4; oo++) {
        int c = o0 + oo;
        #pragma unroll
        for (int nn = 0; nn < 4; nn++) {
            int j = nn0 + nn;
            kdst[idxK(j, c)] = to_tf32(acc[1][oo][nn] + bkv[oo]);
            vdst[idxV(j, c)] = to_tf32(acc[2][oo][nn] + bvv[oo]);
        }
    }
}

// ---------------------------------------------------------------------------
// Kernel 2: mma.sync tf32 flash attention, split-KV.
// 4 warps x 32 query rows; grid (NN/128, BB, NSPLIT) -> 2 CTAs/SM.
// SMEM (floats): Qp[8192] | Kp[4096] | Vp[4096] | Ps[4][2176]
// ---------------------------------------------------------------------------
__global__ void __launch_bounds__(128, 2) attn_mma_kernel()
{
    extern __shared__ float sm[];
    float* Qp = sm;                   // 8192
    float* Kp = sm + 8192;            // 4096
    float* Vp = sm + 8192 + 4096;     // 4096
    float* Ps = sm + 8192 + 8192;     // 4 x 2176

    const int b  = blockIdx.y;
    const int q0 = blockIdx.x * TQa;
    const int sp = blockIdx.z;
    const int tid = threadIdx.x, w = tid >> 5, lam = tid & 31;
    const int g = lam >> 2, tau = lam & 3;
    const uint32_t smK = smem_u32(Kp), smV = smem_u32(Vp);

    // ---- pack Q A-fragments once (warp owns rows w*32 .. w*32+31) ----
    {
        const float* qb = g_q + (size_t)(b * NN + q0 + w * 32) * CC;
        #pragma unroll
        for (int m = 0; m < 2; m++)
            #pragma unroll
            for (int s = 0; s < 8; s++) {
                int ra = m * 16 + g, c = tau + 8 * s;
                float4 f;
                f.x = qb[ra * CC + c];
                f.y = qb[(ra + 8) * CC + c];
                f.z = qb[ra * CC + c + 4];
                f.w = qb[(ra + 8) * CC + c + 4];
                *(float4*)(Qp + w * 2048 + ((m * 8 + s) * 32 + lam) * 4) = f;
            }
    }

    float of[2][8][4];
    #pragma unroll
    for (int m = 0; m < 2; m++)
        #pragma unroll
        for (int t = 0; t < 8; t++)
            #pragma unroll
            for (int c = 0; c < 4; c++) of[m][t][c] = 0.f;
    float lA[2] = {0.f, 0.f};
    float lB[2] = {0.f, 0.f};

    const float* kp = g_kp + ((size_t)b * NTILE + sp * TPS) * 4096;
    const float* vp = g_vp + ((size_t)b * NTILE + sp * TPS) * 4096;
    float* Pw = Ps + w * 2176;

    for (int kt = 0; kt < TPS; kt++) {
        __syncthreads();  // prev tile's K/V fragment reads complete
        {
            const float* ksrc = kp + (size_t)kt * 4096;
            const float* vsrc = vp + (size_t)kt * 4096;
            #pragma unroll
            for (int r = 0; r < 8; r++) {
                int i = tid + 128 * r;
                cp16(smK + i * 16, ksrc + i * 4);
            }
            #pragma unroll
            for (int r = 0; r < 8; r++) {
                int i = tid + 128 * r;
                cp16(smV + i * 16, vsrc + i * 4);
            }
            cp_commit();
            cp_wait0();
        }
        __syncthreads();

        // ---- MMA1: S = Q K^T ----
        float sf[2][8][4];
        #pragma unroll
        for (int m = 0; m < 2; m++)
            #pragma unroll
            for (int t = 0; t < 8; t++)
                #pragma unroll
                for (int c = 0; c < 4; c++) sf[m][t][c] = 0.f;

        #pragma unroll
        for (int s2 = 0; s2 < 4; s2++) {
            uint4 qa0 = *(uint4*)(Qp + w * 2048 + ((0 + 2 * s2)     * 32 + lam) * 4);
            uint4 qa1 = *(uint4*)(Qp + w * 2048 + ((0 + 2 * s2 + 1) * 32 + lam) * 4);
            uint4 qb0 = *(uint4*)(Qp + w * 2048 + ((8 + 2 * s2)     * 32 + lam) * 4);
            uint4 qb1 = *(uint4*)(Qp + w * 2048 + ((8 + 2 * s2 + 1) * 32 + lam) * 4);
            #pragma unroll
            for (int t = 0; t < 8; t++) {
                uint4 kb = *(uint4*)(Kp + ((s2 * 8 + t) * 32 + lam) * 4);
                mma8(sf[0][t], qa0.x, qa0.y, qa0.z, qa0.w, kb.x, kb.y);
                mma8(sf[0][t], qa1.x, qa1.y, qa1.z, qa1.w, kb.z, kb.w);
                mma8(sf[1][t], qb0.x, qb0.y, qb0.z, qb0.w, kb.x, kb.y);
                mma8(sf[1][t], qb1.x, qb1.y, qb1.z, qb1.w, kb.z, kb.w);
            }
        }

        // ---- softmax (no max: |S| << 1); P -> SMEM (tf32) ----
        float rs[2][2] = {{0.f, 0.f}, {0.f, 0.f}};
        #pragma unroll
        for (int m = 0; m < 2; m++)
            #pragma unroll
            for (int t = 0; t < 8; t++) {
                float e0 = __expf(sf[m][t][0]);
                float e1 = __expf(sf[m][t][1]);
                float e2 = __expf(sf[m][t][2]);
                float e3 = __expf(sf[m][t][3]);
                rs[m][0] += e0 + e1;
                rs[m][1] += e2 + e3;
                int row = m * 16 + g, col = 8 * t + 2 * tau;
                *(float2*)(Pw + row * 68 + col)       = make_float2(to_tf32(e0), to_tf32(e1));
                *(float2*)(Pw + (row + 8) * 68 + col) = make_float2(to_tf32(e2), to_tf32(e3));
            }
        #pragma unroll
        for (int m = 0; m < 2; m++) {
            float a = rs[m][0], bsum = rs[m][1];
            a += __shfl_xor_sync(0xffffffffu, a, 1);
            a += __shfl_xor_sync(0xffffffffu, a, 2);
            bsum += __shfl_xor_sync(0xffffffffu, bsum, 1);
            bsum += __shfl_xor_sync(0xffffffffu, bsum, 2);
            lA[m] += a;
            lB[m] += bsum;
        }
        __syncwarp();

        // ---- MMA2: O += P V ----
        #pragma unroll
        for (int s2 = 0; s2 < 4; s2++) {
            uint32_t pa[2][2][4];
            #pragma unroll
            for (int m = 0; m < 2; m++)
                #pragma unroll
                for (int h = 0; h < 2; h++) {
                    int colb = tau + 8 * (2 * s2 + h), row = m * 16 + g;
                    pa[m][h][0] = __float_as_uint(Pw[row * 68 + colb]);
                    pa[m][h][1] = __float_as_uint(Pw[(row + 8) * 68 + colb]);
                    pa[m][h][2] = __float_as_uint(Pw[row * 68 + colb + 4]);
                    pa[m][h][3] = __float_as_uint(Pw[(row + 8) * 68 + colb + 4]);
                }
            #pragma unroll
            for (int t = 0; t < 8; t++) {
                uint4 vb = *(uint4*)(Vp + ((s2 * 8 + t) * 32 + lam) * 4);
                mma8(of[0][t], pa[0][0][0], pa[0][0][1], pa[0][0][2], pa[0][0][3], vb.x, vb.y);
                mma8(of[0][t], pa[0][1][0], pa[0][1][1], pa[0][1][2], pa[0][1][3], vb.z, vb.w);
                mma8(of[1][t], pa[1][0][0], pa[1][0][1], pa[1][0][2], pa[1][0][3], vb.x, vb.y);
                mma8(of[1][t], pa[1][1][0], pa[1][1][1], pa[1][1][2], pa[1][1][3], vb.z, vb.w);
            }
        }
    }

    // ---- epilogue: write unnormalized partials + row sums ----
    float* po = g_po + (size_t)(sp * BB + b) * CC * NN;
    float* pl = g_pl + (size_t)(sp * BB + b) * NN;
    #pragma unroll
    for (int m = 0; m < 2; m++)
        #pragma unroll
        for (int t = 0; t < 8; t++) {
            int rowa = q0 + w * 32 + m * 16 + g;
            int col = 8 * t + 2 * tau;
            po[(size_t)col       * NN + rowa]     = of[m][t][0];
            po[(size_t)(col + 1) * NN + rowa]     = of[m][t][1];
            po[(size_t)col       * NN + rowa + 8] = of[m][t][2];
            po[(size_t)(col + 1) * NN + rowa + 8] = of[m][t][3];
        }
    if (tau == 0) {
        #pragma unroll
        for (int m = 0; m < 2; m++) {
            int rowa = q0 + w * 32 + m * 16 + g;
            pl[rowa]     = lA[m];
            pl[rowa + 8] = lB[m];
        }
    }
}

// ---------------------------------------------------------------------------
// Kernel 3: combine partials: out = (O0 + O1) / (l0 + l1)
// ---------------------------------------------------------------------------
__global__ void __launch_bounds__(256) combine_kernel(float* __restrict__ out)
{
    int idx = blockIdx.x * 256 + threadIdx.x;      // float4 index over B*C*N/4
    int n = (idx * 4) & (NN - 1);
    int b = (idx * 4) >> 18;                       // / (CC*NN)
    float4 a = ((const float4*)g_po)[idx];
    float4 c = ((const float4*)g_po)[BB * CC * NN / 4 + idx];
    const float* l0 = g_pl + (size_t)b * NN + n;
    const float* l1 = g_pl + (size_t)(BB + b) * NN + n;
    float4 o;
    o.x = (a.x + c.x) / (l0[0] + l1[0]);
    o.y = (a.y + c.y) / (l0[1] + l1[1]);
    o.z = (a.z + c.z) / (l0[2] + l1[2]);
    o.w = (a.w + c.w) / (l0[3] + l1[3]);
    ((float4*)out)[idx] = o;
}

// ---------------------------------------------------------------------------
extern "C" void kernel_launch(void* const* d_in, const int* in_sizes, int n_in,
                              void* d_out, int out_size)
{
    const float* x  = (const float*)d_in[0];
    const float* wq = (const float*)d_in[1];
    const float* bq = (const float*)d_in[2];
    const float* wk = (const float*)d_in[3];
    const float* bk = (const float*)d_in[4];
    const float* wv = (const float*)d_in[5];
    const float* bv = (const float*)d_in[6];
    float* out = (float*)d_out;

    const int smem_proj = (CC * 64 + 3 * CC * WSTRIDE) * sizeof(float);
    const int smem_attn = (8192 + 4096 + 4096 + 4 * 2176) * sizeof(float);  // 100352 B
    cudaFuncSetAttribute(proj_kernel, cudaFuncAttributeMaxDynamicSharedMemorySize, smem_proj);
    cudaFuncSetAttribute(attn_mma_kernel, cudaFuncAttributeMaxDynamicSharedMemorySize, smem_attn);

    dim3 gp(NN / 64, BB);
    proj_kernel<<<gp, 256, smem_proj>>>(x, wq, bq, wk, bk, wv, bv);
    dim3 ga(NN / TQa, BB, NSPLIT);
    attn_mma_kernel<<<ga, 128, smem_attn>>>();
    combine_kernel<<<BB * CC * NN / 4 / 256, 256>>>(out);
}

// round 8
// speedup vs baseline: 1.9794x; 1.1612x over previous
#include <cuda_runtime.h>
#include <math.h>
#include <stdint.h>

#define BB 4
#define CC 64
#define NN 4096
#define TQa 128
#define TKa 64
#define WSTRIDE 68
#define NTILE (NN / TKa)   // 64 tiles per batch
#define NSPLIT 2
#define TPS (NTILE / NSPLIT)  // 32 tiles per split

// Scratch (__device__ globals). K/V stored PRE-PACKED in mma-fragment order.
__device__ float g_q[BB * NN * CC];        // (b, n, c) token-major, tf32, log2e/N folded
__device__ float g_kp[BB * NTILE * 4096];  // packed K tiles
__device__ float g_vp[BB * NTILE * 4096];  // packed V tiles
__device__ float g_po[NSPLIT * BB * CC * NN];  // unnormalized O partials
__device__ float g_pl[NSPLIT * BB * NN];       // row-sum partials

// ---------------------------------------------------------------------------
__device__ __forceinline__ float to_tf32(float x) {
    uint32_t u;
    asm("cvt.rna.tf32.f32 %0, %1;" : "=r"(u) : "f"(x));
    return __uint_as_float(u);
}
__device__ __forceinline__ float ex2(float x) {
    float y;
    asm("ex2.approx.ftz.f32 %0, %1;" : "=f"(y) : "f"(x));
    return y;
}
__device__ __forceinline__ uint32_t smem_u32(const void* p) {
    uint32_t a;
    asm("{ .reg .u64 t; cvta.to.shared.u64 t, %1; cvt.u32.u64 %0, t; }" : "=r"(a) : "l"(p));
    return a;
}
__device__ __forceinline__ void cp16(uint32_t dst, const void* src) {
    asm volatile("cp.async.cg.shared.global [%0], [%1], 16;" :: "r"(dst), "l"(src));
}
__device__ __forceinline__ void cp_commit() { asm volatile("cp.async.commit_group;"); }
__device__ __forceinline__ void cp_wait0() { asm volatile("cp.async.wait_group 0;"); }

__device__ __forceinline__ void mma8(float* d, uint32_t a0, uint32_t a1,
                                     uint32_t a2, uint32_t a3,
                                     uint32_t b0, uint32_t b1) {
    asm volatile(
        "mma.sync.aligned.m16n8k8.row.col.f32.tf32.tf32.f32 "
        "{%0,%1,%2,%3}, {%4,%5,%6,%7}, {%8,%9}, {%0,%1,%2,%3};"
        : "+f"(d[0]), "+f"(d[1]), "+f"(d[2]), "+f"(d[3])
        : "r"(a0), "r"(a1), "r"(a2), "r"(a3), "r"(b0), "r"(b1));
}

// Packed-fragment index maps (j = token within 64-tile, c = channel)
__device__ __forceinline__ int idxK(int j, int c) {
    return (((c >> 4) * 8 + (j >> 3)) * 32 + (j & 7) * 4) * 4 + ((c >> 2) & 3) + 4 * (c & 3);
}
__device__ __forceinline__ int idxV(int j, int c) {
    return (((j >> 4) * 8 + (c >> 3)) * 32 + (c & 7) * 4) * 4 + ((j >> 2) & 3) + 4 * (j & 3);
}

// ---------------------------------------------------------------------------
// Kernel 1: fused QKV projection. K/V repacked through SMEM so global stores
// are linear float4 (coalesced).
// ---------------------------------------------------------------------------
__global__ void __launch_bounds__(256) proj_kernel(
    const float* __restrict__ x,
    const float* __restrict__ wq, const float* __restrict__ bq,
    const float* __restrict__ wk, const float* __restrict__ bk,
    const float* __restrict__ wv, const float* __restrict__ bv)
{
    extern __shared__ float sm[];
    float* Xs = sm;               // [C][64]
    float* Ws = sm + CC * 64;     // [3][C][WSTRIDE]

    const int b  = blockIdx.y;
    const int tile = blockIdx.x;
    const int n0 = tile * 64;
    const int tid = threadIdx.x;

    {
        int row = tid >> 2;
        int col = (tid & 3) * 16;
        const float* src = x + ((size_t)(b * CC + row) * NN + n0 + col);
        float* dst = Xs + row * 64 + col;
        #pragma unroll
        for (int k = 0; k < 16; k += 4)
            *(float4*)(dst + k) = *(const float4*)(src + k);
    }
    {
        const float* wsrc[3] = {wq, wk, wv};
        #pragma unroll
        for (int m = 0; m < 3; m++) {
            const float* w = wsrc[m];
            for (int idx = tid; idx < CC * CC; idx += 256) {
                int o = idx >> 6, c = idx & 63;
                Ws[(m * CC + c) * WSTRIDE + o] = w[idx];
            }
        }
    }
    __syncthreads();

    const int ti = tid >> 4, tj = tid & 15;
    const int o0 = ti * 4, nn0 = tj * 4;

    float acc[3][4][4];
    #pragma unroll
    for (int m = 0; m < 3; m++)
        #pragma unroll
        for (int i = 0; i < 4; i++)
            #pragma unroll
            for (int j = 0; j < 4; j++) acc[m][i][j] = 0.f;

    #pragma unroll 4
    for (int c = 0; c < CC; c++) {
        float4 x4 = *(float4*)(Xs + c * 64 + nn0);
        float xv[4] = {x4.x, x4.y, x4.z, x4.w};
        #pragma unroll
        for (int m = 0; m < 3; m++) {
            float4 w4 = *(float4*)(Ws + (m * CC + c) * WSTRIDE + o0);
            float wv_[4] = {w4.x, w4.y, w4.z, w4.w};
            #pragma unroll
            for (int oo = 0; oo < 4; oo++)
                #pragma unroll
                for (int nn = 0; nn < 4; nn++)
                    acc[m][oo][nn] += wv_[oo] * xv[nn];
        }
    }

    // Q scale folds 1/N and log2(e) (softmax uses ex2)
    const float qsc = 1.4426950408889634f / (float)NN;
    float bqv[4], bkv[4], bvv[4];
    #pragma unroll
    for (int oo = 0; oo < 4; oo++) {
        bqv[oo] = bq[o0 + oo];
        bkv[oo] = bk[o0 + oo];
        bvv[oo] = bv[o0 + oo];
    }
    // Q (scaled, tf32) token-major — already coalesced
    #pragma unroll
    for (int nn = 0; nn < 4; nn++) {
        int token = n0 + nn0 + nn;
        float4 qo = make_float4(to_tf32((acc[0][0][nn] + bqv[0]) * qsc),
                                to_tf32((acc[0][1][nn] + bqv[1]) * qsc),
                                to_tf32((acc[0][2][nn] + bqv[2]) * qsc),
                                to_tf32((acc[0][3][nn] + bqv[3]) * qsc));
        *(float4*)(g_q + (size_t)(b * NN + token) * CC + o0) = qo;
    }

    // Repack K/V through SMEM (reuse Xs/Ws region), then coalesced STG
    float* KP = sm;           // 4096 floats
    float* VP = sm + 4096;    // 4096 floats
    __syncthreads();          // all Xs/Ws reads done
    #pragma unroll
    for (int oo = 0; oo < 4; oo++) {
        int c = o0 + oo;
        #pragma unroll
        for (int nn = 0; nn < 4; nn++) {
            int j = nn0 + nn;
            KP[idxK(j, c)] = to_tf32(acc[1][oo][nn] + bkv[oo]);
            VP[idxV(j, c)] = to_tf32(acc[2][oo][nn] + bvv[oo]);
        }
    }
    __syncthreads();
    float* kdst = g_kp + (size_t)(b * NTILE + tile) * 4096;
    float* vdst = g_vp + (size_t)(b * NTILE + tile) * 4096;
    #pragma unroll
    for (int r = 0; r < 4; r++) {
        int i4 = (tid + 256 * r) * 4;
        *(float4*)(kdst + i4) = *(const float4*)(KP + i4);
        *(float4*)(vdst + i4) = *(const float4*)(VP + i4);
    }
}

// ---------------------------------------------------------------------------
// Kernel 2: mma.sync tf32 flash attention, split-KV, double-buffered cp.async,
// P transposed C-frag -> A-frag via quad shuffles (no P SMEM).
// SMEM (floats): Qp[8192] | Kb[2][4096] | Vb[2][4096]  = 96 KB
// ---------------------------------------------------------------------------
__global__ void __launch_bounds__(128, 2) attn_mma_kernel()
{
    extern __shared__ float sm[];
    float* Qp = sm;                   // 8192
    float* Kb = sm + 8192;            // 2 x 4096
    float* Vb = sm + 16384;           // 2 x 4096

    const int b  = blockIdx.y;
    const int q0 = blockIdx.x * TQa;
    const int sp = blockIdx.z;
    const int tid = threadIdx.x, w = tid >> 5, lam = tid & 31;
    const int g = lam >> 2, tau = lam & 3;
    const int sA = tau >> 1, sB = 2 + (tau >> 1);
    const bool odd = tau & 1;
    const uint32_t smK = smem_u32(Kb), smV = smem_u32(Vb);

    // ---- pack Q A-fragments once (warp owns rows w*32 .. w*32+31) ----
    {
        const float* qb = g_q + (size_t)(b * NN + q0 + w * 32) * CC;
        #pragma unroll
        for (int m = 0; m < 2; m++)
            #pragma unroll
            for (int s = 0; s < 8; s++) {
                int ra = m * 16 + g, c = tau + 8 * s;
                float4 f;
                f.x = qb[ra * CC + c];
                f.y = qb[(ra + 8) * CC + c];
                f.z = qb[ra * CC + c + 4];
                f.w = qb[(ra + 8) * CC + c + 4];
                *(float4*)(Qp + w * 2048 + ((m * 8 + s) * 32 + lam) * 4) = f;
            }
    }

    float of[2][8][4];
    #pragma unroll
    for (int m = 0; m < 2; m++)
        #pragma unroll
        for (int t = 0; t < 8; t++)
            #pragma unroll
            for (int c = 0; c < 4; c++) of[m][t][c] = 0.f;
    float lA[2] = {0.f, 0.f};
    float lB[2] = {0.f, 0.f};

    const float* kp = g_kp + ((size_t)b * NTILE + sp * TPS) * 4096;
    const float* vp = g_vp + ((size_t)b * NTILE + sp * TPS) * 4096;

    // prologue: tile 0 -> buffer 0
    #pragma unroll
    for (int r = 0; r < 8; r++) {
        int i = tid + 128 * r;
        cp16(smK + i * 16, kp + i * 4);
        cp16(smV + i * 16, vp + i * 4);
    }
    cp_commit();

    for (int kt = 0; kt < TPS; kt++) {
        cp_wait0();
        __syncthreads();
        if (kt + 1 < TPS) {
            uint32_t nbb = (uint32_t)((kt + 1) & 1) * 16384u;  // byte offset
            const float* ksrc = kp + (size_t)(kt + 1) * 4096;
            const float* vsrc = vp + (size_t)(kt + 1) * 4096;
            #pragma unroll
            for (int r = 0; r < 8; r++) {
                int i = tid + 128 * r;
                cp16(smK + nbb + i * 16, ksrc + i * 4);
                cp16(smV + nbb + i * 16, vsrc + i * 4);
            }
            cp_commit();
        }

        const float* Kp = Kb + (kt & 1) * 4096;
        const float* Vp = Vb + (kt & 1) * 4096;

        // ---- MMA1: S = Q K^T ----
        float sf[2][8][4];
        #pragma unroll
        for (int m = 0; m < 2; m++)
            #pragma unroll
            for (int t = 0; t < 8; t++)
                #pragma unroll
                for (int c = 0; c < 4; c++) sf[m][t][c] = 0.f;

        #pragma unroll
        for (int s2 = 0; s2 < 4; s2++) {
            uint4 qa0 = *(uint4*)(Qp + w * 2048 + ((0 + 2 * s2)     * 32 + lam) * 4);
            uint4 qa1 = *(uint4*)(Qp + w * 2048 + ((0 + 2 * s2 + 1) * 32 + lam) * 4);
            uint4 qb0 = *(uint4*)(Qp + w * 2048 + ((8 + 2 * s2)     * 32 + lam) * 4);
            uint4 qb1 = *(uint4*)(Qp + w * 2048 + ((8 + 2 * s2 + 1) * 32 + lam) * 4);
            #pragma unroll
            for (int t = 0; t < 8; t++) {
                uint4 kb = *(uint4*)(Kp + ((s2 * 8 + t) * 32 + lam) * 4);
                mma8(sf[0][t], qa0.x, qa0.y, qa0.z, qa0.w, kb.x, kb.y);
                mma8(sf[0][t], qa1.x, qa1.y, qa1.z, qa1.w, kb.z, kb.w);
                mma8(sf[1][t], qb0.x, qb0.y, qb0.z, qb0.w, kb.x, kb.y);
                mma8(sf[1][t], qb1.x, qb1.y, qb1.z, qb1.w, kb.z, kb.w);
            }
        }

        // ---- softmax: P = exp2(S) in-place (Q pre-scaled by log2e/N) ----
        float rs[2][2] = {{0.f, 0.f}, {0.f, 0.f}};
        #pragma unroll
        for (int m = 0; m < 2; m++)
            #pragma unroll
            for (int t = 0; t < 8; t++) {
                float e0 = ex2(sf[m][t][0]);
                float e1 = ex2(sf[m][t][1]);
                float e2 = ex2(sf[m][t][2]);
                float e3 = ex2(sf[m][t][3]);
                rs[m][0] += e0 + e1;
                rs[m][1] += e2 + e3;
                sf[m][t][0] = e0; sf[m][t][1] = e1;
                sf[m][t][2] = e2; sf[m][t][3] = e3;
            }
        #pragma unroll
        for (int m = 0; m < 2; m++) {
            float a = rs[m][0], bs = rs[m][1];
            a += __shfl_xor_sync(0xffffffffu, a, 1);
            a += __shfl_xor_sync(0xffffffffu, a, 2);
            bs += __shfl_xor_sync(0xffffffffu, bs, 1);
            bs += __shfl_xor_sync(0xffffffffu, bs, 2);
            lA[m] += a;
            lB[m] += bs;
        }

        // ---- MMA2: O += P V, P A-frags via quad shuffle transpose ----
        #pragma unroll
        for (int s2 = 0; s2 < 4; s2++) {
            uint32_t pa[2][2][4];
            #pragma unroll
            for (int m = 0; m < 2; m++)
                #pragma unroll
                for (int h = 0; h < 2; h++) {
                    const float* e = sf[m][2 * s2 + h];
                    float f0 = __shfl_sync(0xffffffffu, e[0], sA, 4);
                    float f1 = __shfl_sync(0xffffffffu, e[1], sA, 4);
                    float f2 = __shfl_sync(0xffffffffu, e[2], sA, 4);
                    float f3 = __shfl_sync(0xffffffffu, e[3], sA, 4);
                    float h0 = __shfl_sync(0xffffffffu, e[0], sB, 4);
                    float h1 = __shfl_sync(0xffffffffu, e[1], sB, 4);
                    float h2 = __shfl_sync(0xffffffffu, e[2], sB, 4);
                    float h3 = __shfl_sync(0xffffffffu, e[3], sB, 4);
                    pa[m][h][0] = __float_as_uint(to_tf32(odd ? f1 : f0));
                    pa[m][h][1] = __float_as_uint(to_tf32(odd ? f3 : f2));
                    pa[m][h][2] = __float_as_uint(to_tf32(odd ? h1 : h0));
                    pa[m][h][3] = __float_as_uint(to_tf32(odd ? h3 : h2));
                }
            #pragma unroll
            for (int t = 0; t < 8; t++) {
                uint4 vb = *(uint4*)(Vp + ((s2 * 8 + t) * 32 + lam) * 4);
                mma8(of[0][t], pa[0][0][0], pa[0][0][1], pa[0][0][2], pa[0][0][3], vb.x, vb.y);
                mma8(of[0][t], pa[0][1][0], pa[0][1][1], pa[0][1][2], pa[0][1][3], vb.z, vb.w);
                mma8(of[1][t], pa[1][0][0], pa[1][0][1], pa[1][0][2], pa[1][0][3], vb.x, vb.y);
                mma8(of[1][t], pa[1][1][0], pa[1][1][1], pa[1][1][2], pa[1][1][3], vb.z, vb.w);
            }
        }
    }

    // ---- epilogue: write unnormalized partials + row sums ----
    float* po = g_po + (size_t)(sp * BB + b) * CC * NN;
    float* pl = g_pl + (size_t)(sp * BB + b) * NN;
    #pragma unroll
    for (int m = 0; m < 2; m++)
        #pragma unroll
        for (int t = 0; t < 8; t++) {
            int rowa = q0 + w * 32 + m * 16 + g;
            int col = 8 * t + 2 * tau;
            po[(size_t)col       * NN + rowa]     = of[m][t][0];
            po[(size_t)(col + 1) * NN + rowa]     = of[m][t][1];
            po[(size_t)col       * NN + rowa + 8] = of[m][t][2];
            po[(size_t)(col + 1) * NN + rowa + 8] = of[m][t][3];
        }
    if (tau == 0) {
        #pragma unroll
        for (int m = 0; m < 2; m++) {
            int rowa = q0 + w * 32 + m * 16 + g;
            pl[rowa]     = lA[m];
            pl[rowa + 8] = lB[m];
        }
    }
}

// ---------------------------------------------------------------------------
// Kernel 3: combine partials: out = (O0 + O1) / (l0 + l1)
// ---------------------------------------------------------------------------
__global__ void __launch_bounds__(256) combine_kernel(float* __restrict__ out)
{
    int idx = blockIdx.x * 256 + threadIdx.x;      // float4 index over B*C*N/4
    int n = (idx * 4) & (NN - 1);
    int b = (idx * 4) >> 18;                       // / (CC*NN)
    float4 a = ((const float4*)g_po)[idx];
    float4 c = ((const float4*)g_po)[BB * CC * NN / 4 + idx];
    const float* l0 = g_pl + (size_t)b * NN + n;
    const float* l1 = g_pl + (size_t)(BB + b) * NN + n;
    float4 o;
    o.x = (a.x + c.x) / (l0[0] + l1[0]);
    o.y = (a.y + c.y) / (l0[1] + l1[1]);
    o.z = (a.z + c.z) / (l0[2] + l1[2]);
    o.w = (a.w + c.w) / (l0[3] + l1[3]);
    ((float4*)out)[idx] = o;
}

// ---------------------------------------------------------------------------
extern "C" void kernel_launch(void* const* d_in, const int* in_sizes, int n_in,
                              void* d_out, int out_size)
{
    const float* x  = (const float*)d_in[0];
    const float* wq = (const float*)d_in[1];
    const float* bq = (const float*)d_in[2];
    const float* wk = (const float*)d_in[3];
    const float* bk = (const float*)d_in[4];
    const float* wv = (const float*)d_in[5];
    const float* bv = (const float*)d_in[6];
    float* out = (float*)d_out;

    const int smem_proj = (CC * 64 + 3 * CC * WSTRIDE) * sizeof(float);
    const int smem_attn = (8192 + 8192 + 8192) * sizeof(float);  // 98304 B
    cudaFuncSetAttribute(proj_kernel, cudaFuncAttributeMaxDynamicSharedMemorySize, smem_proj);
    cudaFuncSetAttribute(attn_mma_kernel, cudaFuncAttributeMaxDynamicSharedMemorySize, smem_attn);

    dim3 gp(NN / 64, BB);
    proj_kernel<<<gp, 256, smem_proj>>>(x, wq, bq, wk, bk, wv, bv);
    dim3 ga(NN / TQa, BB, NSPLIT);
    attn_mma_kernel<<<ga, 128, smem_attn>>>();
    combine_kernel<<<BB * CC * NN / 4 / 256, 256>>>(out);
}

// round 11
// speedup vs baseline: 3.4469x; 1.7414x over previous
#include <cuda_runtime.h>
#include <cuda_fp16.h>
#include <math.h>
#include <stdint.h>

#define BB 4
#define CC 64
#define NN 4096
#define TQa 128
#define TKa 64
#define WSTRIDE 68
#define NTILE (NN / TKa)      // 64 tiles per batch
#define NSPLIT 2
#define TPS (NTILE / NSPLIT)  // 32 tiles per split

// Scratch (__device__ globals). K/V stored PRE-PACKED (fp16) in mma-fragment order.
__device__ __half    g_qh[BB * NN * CC];        // (b, n, c) token-major fp16 (natural scale)
__device__ uint32_t  g_kph[BB * NTILE * 2048];  // packed K tiles (half2 regs)
__device__ uint32_t  g_vph[BB * NTILE * 2048];  // packed V tiles
__device__ float     g_po[NSPLIT * BB * CC * NN];  // unnormalized O partials
__device__ float     g_pl[NSPLIT * BB * NN];       // row-sum partials

// ---------------------------------------------------------------------------
__device__ __forceinline__ float ex2(float x) {
    float y;
    asm("ex2.approx.ftz.f32 %0, %1;" : "=f"(y) : "f"(x));
    return y;
}
__device__ __forceinline__ uint32_t h2(float lo, float hi) {
    __half2 h = __floats2half2_rn(lo, hi);   // lo -> .x (low half), hi -> .y (high half)
    return *(uint32_t*)&h;
}
__device__ __forceinline__ uint32_t smem_u32(const void* p) {
    uint32_t a;
    asm("{ .reg .u64 t; cvta.to.shared.u64 t, %1; cvt.u32.u64 %0, t; }" : "=r"(a) : "l"(p));
    return a;
}
__device__ __forceinline__ void cp16(uint32_t dst, const void* src) {
    asm volatile("cp.async.cg.shared.global [%0], [%1], 16;" :: "r"(dst), "l"(src));
}
__device__ __forceinline__ void cp_commit() { asm volatile("cp.async.commit_group;"); }
__device__ __forceinline__ void cp_wait0() { asm volatile("cp.async.wait_group 0;"); }

// fp16 m16n8k16 mma, fp32 accumulate
__device__ __forceinline__ void mma16(float* d, const uint32_t* a,
                                      uint32_t b0, uint32_t b1) {
    asm volatile(
        "mma.sync.aligned.m16n8k16.row.col.f32.f16.f16.f32 "
        "{%0,%1,%2,%3}, {%4,%5,%6,%7}, {%8,%9}, {%0,%1,%2,%3};"
        : "+f"(d[0]), "+f"(d[1]), "+f"(d[2]), "+f"(d[3])
        : "r"(a[0]), "r"(a[1]), "r"(a[2]), "r"(a[3]), "r"(b0), "r"(b1));
}

// ---------------------------------------------------------------------------
// Kernel 1: fused QKV projection; K/V packed (fp16 fragment order) via SMEM.
// ---------------------------------------------------------------------------
__global__ void __launch_bounds__(256) proj_kernel(
    const float* __restrict__ x,
    const float* __restrict__ wq, const float* __restrict__ bq,
    const float* __restrict__ wk, const float* __restrict__ bk,
    const float* __restrict__ wv, const float* __restrict__ bv)
{
    extern __shared__ float sm[];
    float* Xs = sm;               // [C][64]
    float* Ws = sm + CC * 64;     // [3][C][WSTRIDE]

    const int b  = blockIdx.y;
    const int tile = blockIdx.x;
    const int n0 = tile * 64;
    const int tid = threadIdx.x;

    {
        int row = tid >> 2;
        int col = (tid & 3) * 16;
        const float* src = x + ((size_t)(b * CC + row) * NN + n0 + col);
        float* dst = Xs + row * 64 + col;
        #pragma unroll
        for (int k = 0; k < 16; k += 4)
            *(float4*)(dst + k) = *(const float4*)(src + k);
    }
    {
        const float* wsrc[3] = {wq, wk, wv};
        #pragma unroll
        for (int m = 0; m < 3; m++) {
            const float* w = wsrc[m];
            for (int idx = tid; idx < CC * CC; idx += 256) {
                int o = idx >> 6, c = idx & 63;
                Ws[(m * CC + c) * WSTRIDE + o] = w[idx];
            }
        }
    }
    __syncthreads();

    const int ti = tid >> 4, tj = tid & 15;
    const int o0 = ti * 4, nn0 = tj * 4;

    float acc[3][4][4];
    #pragma unroll
    for (int m = 0; m < 3; m++)
        #pragma unroll
        for (int i = 0; i < 4; i++)
            #pragma unroll
            for (int j = 0; j < 4; j++) acc[m][i][j] = 0.f;

    #pragma unroll 4
    for (int c = 0; c < CC; c++) {
        float4 x4 = *(float4*)(Xs + c * 64 + nn0);
        float xv[4] = {x4.x, x4.y, x4.z, x4.w};
        #pragma unroll
        for (int m = 0; m < 3; m++) {
            float4 w4 = *(float4*)(Ws + (m * CC + c) * WSTRIDE + o0);
            float wv_[4] = {w4.x, w4.y, w4.z, w4.w};
            #pragma unroll
            for (int oo = 0; oo < 4; oo++)
                #pragma unroll
                for (int nn = 0; nn < 4; nn++)
                    acc[m][oo][nn] += wv_[oo] * xv[nn];
        }
    }

    float bqv[4], bkv[4], bvv[4];
    #pragma unroll
    for (int oo = 0; oo < 4; oo++) {
        bqv[oo] = bq[o0 + oo];
        bkv[oo] = bk[o0 + oo];
        bvv[oo] = bv[o0 + oo];
    }
    // Q token-major fp16 (channels o0,o0+1 / o0+2,o0+3 as half2)
    {
        uint32_t* q32 = (uint32_t*)g_qh;
        #pragma unroll
        for (int nn = 0; nn < 4; nn++) {
            int token = n0 + nn0 + nn;
            size_t base = (size_t)(b * NN + token) * (CC / 2) + (o0 >> 1);
            q32[base]     = h2(acc[0][0][nn] + bqv[0], acc[0][1][nn] + bqv[1]);
            q32[base + 1] = h2(acc[0][2][nn] + bqv[2], acc[0][3][nn] + bqv[3]);
        }
    }

    // K/V fragment packing through SMEM (reuse Xs/Ws region)
    __half* KPh = (__half*)sm;            // 4096 halves (8 KB)
    __half* VPh = (__half*)sm + 4096;     // 4096 halves
    __syncthreads();
    #pragma unroll
    for (int oo = 0; oo < 4; oo++) {
        int c = o0 + oo;
        #pragma unroll
        for (int nn = 0; nn < 4; nn++) {
            int j = nn0 + nn;
            {   // K: B-frag of MMA1 (k=channel, n=token)
                int s = c >> 4, t = j >> 3;
                int lamk = 4 * (j & 7) + ((c >> 1) & 3);
                int breg = (c >> 3) & 1;
                int u32i = ((s * 4 + (t >> 1)) * 32 + lamk) * 4 + (t & 1) * 2 + breg;
                KPh[u32i * 2 + (c & 1)] = __float2half_rn(acc[1][oo][nn] + bkv[oo]);
            }
            {   // V: B-frag of MMA2 (k=token, n=channel)
                int s = j >> 4, t = c >> 3;
                int lamv = 4 * (c & 7) + ((j >> 1) & 3);
                int breg = (j >> 3) & 1;
                int u32i = ((s * 4 + (t >> 1)) * 32 + lamv) * 4 + (t & 1) * 2 + breg;
                VPh[u32i * 2 + (j & 1)] = __float2half_rn(acc[2][oo][nn] + bvv[oo]);
            }
        }
    }
    __syncthreads();
    // Coalesced copy out (2048 u32 each = 512 uint4)
    {
        const uint4* ks = (const uint4*)KPh;
        const uint4* vs = (const uint4*)VPh;
        uint4* kdst = (uint4*)(g_kph + (size_t)(b * NTILE + tile) * 2048);
        uint4* vdst = (uint4*)(g_vph + (size_t)(b * NTILE + tile) * 2048);
        #pragma unroll
        for (int r = 0; r < 2; r++) {
            int i = tid + 256 * r;
            kdst[i] = ks[i];
            vdst[i] = vs[i];
        }
    }
}

// ---------------------------------------------------------------------------
// Kernel 2: fp16 m16n8k16 flash attention, split-KV, double-buffered cp.async.
// 4 warps x 32 query rows. Q frags in registers. P: C-frag == A-frag (cvt only).
// SMEM (u32): Kb[2][2048] | Vb[2][2048] = 32 KB
// ---------------------------------------------------------------------------
__global__ void __launch_bounds__(128, 2) attn_mma_kernel()
{
    extern __shared__ uint32_t smu[];
    uint32_t* Kb = smu;           // 2 x 2048
    uint32_t* Vb = smu + 4096;    // 2 x 2048

    const int b  = blockIdx.y;
    const int q0 = blockIdx.x * TQa;
    const int sp = blockIdx.z;
    const int tid = threadIdx.x, w = tid >> 5, lam = tid & 31;
    const int g = lam >> 2, tau = lam & 3;
    const uint32_t smK = smem_u32(Kb), smV = smem_u32(Vb);
    const float SC = 1.4426950408889634f / (float)NN;  // log2(e)/N

    // ---- Q A-fragments in registers: qa[m][s][0..3] ----
    uint32_t qa[2][4][4];
    {
        const uint32_t* q32 = (const uint32_t*)g_qh;
        #pragma unroll
        for (int m = 0; m < 2; m++) {
            size_t rg  = (size_t)(b * NN + q0 + w * 32 + m * 16 + g) * 32;
            size_t rg8 = rg + 8 * 32;
            #pragma unroll
            for (int s = 0; s < 4; s++) {
                qa[m][s][0] = q32[rg  + 8 * s + tau];
                qa[m][s][1] = q32[rg8 + 8 * s + tau];
                qa[m][s][2] = q32[rg  + 8 * s + tau + 4];
                qa[m][s][3] = q32[rg8 + 8 * s + tau + 4];
            }
        }
    }

    float of[2][8][4];
    #pragma unroll
    for (int m = 0; m < 2; m++)
        #pragma unroll
        for (int t = 0; t < 8; t++)
            #pragma unroll
            for (int c = 0; c < 4; c++) of[m][t][c] = 0.f;
    float lA[2] = {0.f, 0.f};
    float lB[2] = {0.f, 0.f};

    const uint32_t* kp = g_kph + ((size_t)b * NTILE + sp * TPS) * 2048;
    const uint32_t* vp = g_vph + ((size_t)b * NTILE + sp * TPS) * 2048;

    // prologue: tile 0 -> buffer 0 (512 cp16 total per array)
    #pragma unroll
    for (int r = 0; r < 4; r++) {
        int i = tid + 128 * r;
        cp16(smK + i * 16, kp + i * 4);
        cp16(smV + i * 16, vp + i * 4);
    }
    cp_commit();

    for (int kt = 0; kt < TPS; kt++) {
        cp_wait0();
        __syncthreads();
        if (kt + 1 < TPS) {
            uint32_t nbb = (uint32_t)((kt + 1) & 1) * 8192u;  // byte offset of buffer
            const uint32_t* ksrc = kp + (size_t)(kt + 1) * 2048;
            const uint32_t* vsrc = vp + (size_t)(kt + 1) * 2048;
            #pragma unroll
            for (int r = 0; r < 4; r++) {
                int i = tid + 128 * r;
                cp16(smK + nbb + i * 16, ksrc + i * 4);
                cp16(smV + nbb + i * 16, vsrc + i * 4);
            }
            cp_commit();
        }

        const uint4* Kp4 = (const uint4*)(Kb + (kt & 1) * 2048);
        const uint4* Vp4 = (const uint4*)(Vb + (kt & 1) * 2048);

        // ---- MMA1: S = Q K^T  (2m x 8t x 4s = 64 mma16) ----
        float sf[2][8][4];
        #pragma unroll
        for (int m = 0; m < 2; m++)
            #pragma unroll
            for (int t = 0; t < 8; t++)
                #pragma unroll
                for (int c = 0; c < 4; c++) sf[m][t][c] = 0.f;

        #pragma unroll
        for (int s = 0; s < 4; s++)
            #pragma unroll
            for (int tp = 0; tp < 4; tp++) {
                uint4 kb = Kp4[(s * 4 + tp) * 32 + lam];
                mma16(sf[0][2 * tp],     qa[0][s], kb.x, kb.y);
                mma16(sf[0][2 * tp + 1], qa[0][s], kb.z, kb.w);
                mma16(sf[1][2 * tp],     qa[1][s], kb.x, kb.y);
                mma16(sf[1][2 * tp + 1], qa[1][s], kb.z, kb.w);
            }

        // ---- softmax: P = exp2(S * SC); C-frag layout == A-frag layout ----
        float rs[2][2] = {{0.f, 0.f}, {0.f, 0.f}};
        #pragma unroll
        for (int m = 0; m < 2; m++)
            #pragma unroll
            for (int t = 0; t < 8; t++) {
                float e0 = ex2(sf[m][t][0] * SC);
                float e1 = ex2(sf[m][t][1] * SC);
                float e2 = ex2(sf[m][t][2] * SC);
                float e3 = ex2(sf[m][t][3] * SC);
                rs[m][0] += e0 + e1;
                rs[m][1] += e2 + e3;
                sf[m][t][0] = e0; sf[m][t][1] = e1;
                sf[m][t][2] = e2; sf[m][t][3] = e3;
            }
        #pragma unroll
        for (int m = 0; m < 2; m++) {
            float a = rs[m][0], bs = rs[m][1];
            a += __shfl_xor_sync(0xffffffffu, a, 1);
            a += __shfl_xor_sync(0xffffffffu, a, 2);
            bs += __shfl_xor_sync(0xffffffffu, bs, 1);
            bs += __shfl_xor_sync(0xffffffffu, bs, 2);
            lA[m] += a;
            lB[m] += bs;
        }

        // P A-fragments: pure cvt (a0..a3 = c0..c3 of n8-tiles 2s, 2s+1)
        uint32_t pa[2][4][4];
        #pragma unroll
        for (int m = 0; m < 2; m++)
            #pragma unroll
            for (int s = 0; s < 4; s++) {
                pa[m][s][0] = h2(sf[m][2 * s][0],     sf[m][2 * s][1]);
                pa[m][s][1] = h2(sf[m][2 * s][2],     sf[m][2 * s][3]);
                pa[m][s][2] = h2(sf[m][2 * s + 1][0], sf[m][2 * s + 1][1]);
                pa[m][s][3] = h2(sf[m][2 * s + 1][2], sf[m][2 * s + 1][3]);
            }

        // ---- MMA2: O += P V  (64 mma16) ----
        #pragma unroll
        for (int s = 0; s < 4; s++)
            #pragma unroll
            for (int tp = 0; tp < 4; tp++) {
                uint4 vb = Vp4[(s * 4 + tp) * 32 + lam];
                mma16(of[0][2 * tp],     pa[0][s], vb.x, vb.y);
                mma16(of[0][2 * tp + 1], pa[0][s], vb.z, vb.w);
                mma16(of[1][2 * tp],     pa[1][s], vb.x, vb.y);
                mma16(of[1][2 * tp + 1], pa[1][s], vb.z, vb.w);
            }
    }

    // ---- epilogue: unnormalized partials + row sums ----
    float* po = g_po + (size_t)(sp * BB + b) * CC * NN;
    float* pl = g_pl + (size_t)(sp * BB + b) * NN;
    #pragma unroll
    for (int m = 0; m < 2; m++)
        #pragma unroll
        for (int t = 0; t < 8; t++) {
            int rowa = q0 + w * 32 + m * 16 + g;
            int col = 8 * t + 2 * tau;
            po[(size_t)col       * NN + rowa]     = of[m][t][0];
            po[(size_t)(col + 1) * NN + rowa]     = of[m][t][1];
            po[(size_t)col       * NN + rowa + 8] = of[m][t][2];
            po[(size_t)(col + 1) * NN + rowa + 8] = of[m][t][3];
        }
    if (tau == 0) {
        #pragma unroll
        for (int m = 0; m < 2; m++) {
            int rowa = q0 + w * 32 + m * 16 + g;
            pl[rowa]     = lA[m];
            pl[rowa + 8] = lB[m];
        }
    }
}

// ---------------------------------------------------------------------------
// Kernel 3: combine partials: out = (O0 + O1) / (l0 + l1)
// ---------------------------------------------------------------------------
__global__ void __launch_bounds__(256) combine_kernel(float* __restrict__ out)
{
    int idx = blockIdx.x * 256 + threadIdx.x;      // float4 index over B*C*N/4
    int n = (idx * 4) & (NN - 1);
    int b = (idx * 4) >> 18;                       // / (CC*NN)
    float4 a = ((const float4*)g_po)[idx];
    float4 c = ((const float4*)g_po)[BB * CC * NN / 4 + idx];
    const float* l0 = g_pl + (size_t)b * NN + n;
    const float* l1 = g_pl + (size_t)(BB + b) * NN + n;
    float4 o;
    o.x = (a.x + c.x) / (l0[0] + l1[0]);
    o.y = (a.y + c.y) / (l0[1] + l1[1]);
    o.z = (a.z + c.z) / (l0[2] + l1[2]);
    o.w = (a.w + c.w) / (l0[3] + l1[3]);
    ((float4*)out)[idx] = o;
}

// ---------------------------------------------------------------------------
extern "C" void kernel_launch(void* const* d_in, const int* in_sizes, int n_in,
                              void* d_out, int out_size)
{
    const float* x  = (const float*)d_in[0];
    const float* wq = (const float*)d_in[1];
    const float* bq = (const float*)d_in[2];
    const float* wk = (const float*)d_in[3];
    const float* bk = (const float*)d_in[4];
    const float* wv = (const float*)d_in[5];
    const float* bv = (const float*)d_in[6];
    float* out = (float*)d_out;

    const int smem_proj = (CC * 64 + 3 * CC * WSTRIDE) * sizeof(float);
    const int smem_attn = (4096 + 4096) * sizeof(uint32_t);  // 32768 B
    cudaFuncSetAttribute(proj_kernel, cudaFuncAttributeMaxDynamicSharedMemorySize, smem_proj);
    cudaFuncSetAttribute(attn_mma_kernel, cudaFuncAttributeMaxDynamicSharedMemorySize, smem_attn);

    dim3 gp(NN / 64, BB);
    proj_kernel<<<gp, 256, smem_proj>>>(x, wq, bq, wk, bk, wv, bv);
    dim3 ga(NN / TQa, BB, NSPLIT);
    attn_mma_kernel<<<ga, 128, smem_attn>>>();
    combine_kernel<<<BB * CC * NN / 4 / 256, 256>>>(out);
}